// round 14
// baseline (speedup 1.0000x reference)
#include <cuda_runtime.h>
#include <cuda_bf16.h>
#include <cstdint>

// ---------------------------------------------------------------------------
// Problem constants
// ---------------------------------------------------------------------------
#define T_STEPS   1024
#define BATCH     64
#define N_IN      256
#define N_HID     512
#define M_TOTAL   (T_STEPS * BATCH)       // 65536
#define YN        (BATCH * N_HID)         // 32768

#define GAIN_REC  0.04419417382415922f    // 1/sqrt(512)
#define DT_H      0.1f

__device__ float g_ext[(size_t)M_TOTAL * N_HID];   // inputs @ W_ih + b_ih

__device__ __forceinline__ void ffma2(unsigned long long& acc,
                                      unsigned long long a,
                                      unsigned long long b) {
    asm("fma.rn.f32x2 %0, %1, %2, %0;" : "+l"(acc) : "l"(a), "l"(b));
}
__device__ __forceinline__ unsigned long long pack2(float a) {
    unsigned long long r;
    asm("mov.b64 %0, {%1, %1};" : "=l"(r) : "f"(a));
    return r;
}

// ---------------------------------------------------------------------------
// Kernel A: ext = inputs @ W_ih + b_ih   (M=65536, N=512, K=256)
//   64x128 tile, 256 threads, 4x8 outputs/thread held as f32x2 pairs,
//   register-prefetch pipeline. Pure fp32 math (FFMA2 = 2 exact fp32 FMAs).
// ---------------------------------------------------------------------------
#define TA_M 64
#define TA_N 128
#define TA_K 32

__global__ __launch_bounds__(256) void ext_gemm_kernel(
    const float* __restrict__ A, const float* __restrict__ W,
    const float* __restrict__ bias)
{
    __shared__ float As[TA_K][TA_M + 4];   // k-major, padded
    __shared__ float Bs[TA_K][TA_N];

    const int tid = threadIdx.x;
    const int tx  = tid & 15;              // 16 col-groups of 8
    const int ty  = tid >> 4;              // 16 row-groups of 4
    const int m0  = blockIdx.y * TA_M;
    const int n0  = blockIdx.x * TA_N;

    // per-thread load coords (2 A chunks, 4 B chunks per tile)
    int aR[2], aC[2], bR[4], bC[4];
#pragma unroll
    for (int j = 0; j < 2; ++j) {
        int f = tid + j * 256;
        aR[j] = f >> 3;  aC[j] = f & 7;
    }
#pragma unroll
    for (int j = 0; j < 4; ++j) {
        int f = tid + j * 256;
        bR[j] = f >> 5;  bC[j] = f & 31;
    }

    unsigned long long acc2[4][4];         // [row][colpair] = 2 fp32 each
#pragma unroll
    for (int i = 0; i < 4; ++i)
#pragma unroll
        for (int j = 0; j < 4; ++j) acc2[i][j] = 0ull;

    // prefetch tile 0 into registers
    float4 ra[2], rb[4];
#pragma unroll
    for (int j = 0; j < 2; ++j)
        ra[j] = *(const float4*)&A[(size_t)(m0 + aR[j]) * N_IN + aC[j] * 4];
#pragma unroll
    for (int j = 0; j < 4; ++j)
        rb[j] = *(const float4*)&W[(size_t)bR[j] * N_HID + n0 + bC[j] * 4];

    for (int kt = 0; kt < N_IN; kt += TA_K) {
        // commit prefetched regs to smem
#pragma unroll
        for (int j = 0; j < 2; ++j) {
            As[aC[j] * 4 + 0][aR[j]] = ra[j].x;
            As[aC[j] * 4 + 1][aR[j]] = ra[j].y;
            As[aC[j] * 4 + 2][aR[j]] = ra[j].z;
            As[aC[j] * 4 + 3][aR[j]] = ra[j].w;
        }
#pragma unroll
        for (int j = 0; j < 4; ++j)
            *(float4*)&Bs[bR[j]][bC[j] * 4] = rb[j];
        __syncthreads();

        // prefetch next tile while computing this one
        if (kt + TA_K < N_IN) {
#pragma unroll
            for (int j = 0; j < 2; ++j)
                ra[j] = *(const float4*)&A[(size_t)(m0 + aR[j]) * N_IN
                                           + kt + TA_K + aC[j] * 4];
#pragma unroll
            for (int j = 0; j < 4; ++j)
                rb[j] = *(const float4*)&W[(size_t)(kt + TA_K + bR[j]) * N_HID
                                           + n0 + bC[j] * 4];
        }

#pragma unroll
        for (int k = 0; k < TA_K; ++k) {
            float a[4];
            *(float4*)a = *(const float4*)&As[k][ty * 4];
            const float* brow = &Bs[k][tx * 8];
            ulonglong2 b0 = *(const ulonglong2*)brow;        // cols 0-3
            ulonglong2 b1 = *(const ulonglong2*)(brow + 4);  // cols 4-7
#pragma unroll
            for (int i = 0; i < 4; ++i) {
                unsigned long long pa = pack2(a[i]);
                ffma2(acc2[i][0], pa, b0.x);
                ffma2(acc2[i][1], pa, b0.y);
                ffma2(acc2[i][2], pa, b1.x);
                ffma2(acc2[i][3], pa, b1.y);
            }
        }
        __syncthreads();
    }

    // epilogue: add bias, store 8 cols per row
    float bv[8];
    *(float4*)&bv[0] = *(const float4*)&bias[n0 + tx * 8];
    *(float4*)&bv[4] = *(const float4*)&bias[n0 + tx * 8 + 4];
#pragma unroll
    for (int i = 0; i < 4; ++i) {
        int m = m0 + ty * 4 + i;
        float o[8];
#pragma unroll
        for (int j = 0; j < 4; ++j) {
            float2 f = *(float2*)&acc2[i][j];
            o[j * 2]     = f.x + bv[j * 2];
            o[j * 2 + 1] = f.y + bv[j * 2 + 1];
        }
        *(float4*)&g_ext[(size_t)m * N_HID + n0 + tx * 8]     = *(float4*)&o[0];
        *(float4*)&g_ext[(size_t)m * N_HID + n0 + tx * 8 + 4] = *(float4*)&o[4];
    }
}

// ---------------------------------------------------------------------------
// Kernel B: persistent recurrence — BYTE-IDENTICAL to round 13 (3904us).
//   16 clusters x 8 CTAs, 768 threads; dot warps 0-15, dyn warps 16-23;
//   per-source tx-mbarriers + eager per-warp 128B bulk S2S broadcast.
// ---------------------------------------------------------------------------
#define RNT 768

#define WS_F    0                      // W slice [k4][hl] float4: 32768 floats
#define YS_F    32768                  // 2 bufs x [src(8)][row(4)][64]: 4096 f
#define RED_F   36864                  // 2 bufs x [kh(8)][row(4)][hl(64)]: 4096
#define STAG_F  40960                  // yn staging [row*64+hl]: 256 floats
#define MBAR_F  41216                  // 16 mbarriers (128 B)
#define SMEM_R_BYTES ((MBAR_F + 32) * 4)

#define TX_BYTES   1024u               // per source CTA per dest (8 x 128B)
#define CHUNK_B    128u                // per dyn-warp chunk

__device__ __forceinline__ void mbar_init(uint32_t a, uint32_t cnt) {
    asm volatile("mbarrier.init.shared.b64 [%0], %1;" :: "r"(a), "r"(cnt) : "memory");
}
__device__ __forceinline__ void mbar_expect_tx(uint32_t a, uint32_t bytes) {
    asm volatile("mbarrier.arrive.expect_tx.shared.b64 _, [%0], %1;"
                 :: "r"(a), "r"(bytes) : "memory");
}
__device__ __forceinline__ void mbar_wait_parity(uint32_t a, uint32_t par) {
    asm volatile("{\n\t.reg .pred P;\n\t"
                 "WL_%=:\n\t"
                 "mbarrier.try_wait.parity.acquire.cluster.shared::cta.b64 P, [%0], %1, 0x989680;\n\t"
                 "@P bra WD_%=;\n\t"
                 "bra WL_%=;\n\t"
                 "WD_%=:\n\t}"
                 :: "r"(a), "r"(par) : "memory");
}
__device__ __forceinline__ void bulk_s2s_128(uint32_t dstLocal, uint32_t srcLocal,
                                             uint32_t mbarLocal, uint32_t rank) {
    asm volatile("{\n\t.reg .b32 rd, rm;\n\t"
                 "mapa.shared::cluster.u32 rd, %0, %3;\n\t"
                 "mapa.shared::cluster.u32 rm, %2, %3;\n\t"
                 "cp.async.bulk.shared::cluster.shared::cta.mbarrier::complete_tx::bytes "
                 "[rd], [%1], %4, [rm];\n\t}"
                 :: "r"(dstLocal), "r"(srcLocal), "r"(mbarLocal), "r"(rank),
                    "n"(CHUNK_B)
                 : "memory");
}
__device__ __forceinline__ float tanh_approx(float x) {
    float r;
    asm("tanh.approx.f32 %0, %1;" : "=f"(r) : "f"(x));
    return r;
}

__global__ void __cluster_dims__(8, 1, 1) __launch_bounds__(RNT, 1)
horn_rec14(const float* __restrict__ W_hh,
           const float* __restrict__ b_hh,
           const float* __restrict__ alpha,
           const float* __restrict__ omega,
           const float* __restrict__ gamma,
           const float* __restrict__ vvec,
           float* __restrict__ out)
{
    extern __shared__ float smem[];

    const int tid  = threadIdx.x;
    const int bg   = blockIdx.x >> 3;           // cluster id (16)
    const int rank = blockIdx.x & 7;            // h0 = rank*64
    const int h0   = rank * 64;
    const int warp = tid >> 5;
    const int lane = tid & 31;
    const uint32_t smem_u32 = (uint32_t)__cvta_generic_to_shared(smem);
    const uint32_t mbar_base = smem_u32 + MBAR_F * 4;   // mbar[r][p] stride 8B

    // ---- fill W slice: ws[k4*256 + col*4 + (k&3)] (float4 packs a k-quad) ----
    for (int idx = tid; idx < 64 * N_HID; idx += RNT) {
        int k = idx >> 6;
        int l = idx & 63;
        smem[WS_F + (k >> 2) * 256 + l * 4 + (k & 3)] =
            W_hh[(size_t)k * N_HID + h0 + l];
    }

    if (tid < 16) mbar_init(mbar_base + tid * 8, 1);
    __syncthreads();
    if (tid < 16) mbar_expect_tx(mbar_base + tid * 8, TX_BYTES);
    __syncthreads();
    asm volatile("barrier.cluster.arrive.aligned;" ::: "memory");
    asm volatile("barrier.cluster.wait.aligned;"   ::: "memory");

    if (warp < 16) {
        // =================== DOT WARPS (tid 0..511) ===================
        const int kh = tid >> 6;                // k-slice = source rank 0..7
        const int hl = tid & 63;
        const ulonglong2* wp = ((const ulonglong2*)smem) + (kh * 16) * 64 + hl;
        float* red0 = smem + RED_F + kh * 256 + hl;

        for (int t = 0; t < T_STEPS; ++t) {
            if (t > 0) {
                const int p = (t - 1) & 1;
                const uint32_t mb = mbar_base + (kh * 2 + p) * 8;
                mbar_wait_parity(mb, (unsigned)(((t - 1) >> 1) & 1));
                if ((tid & 63) == 0) mbar_expect_tx(mb, TX_BYTES);

                // y block from source rank kh: [row(4)][64]
                const ulonglong2* yb = ((const ulonglong2*)
                    (smem + YS_F + p * 2048)) + kh * 64;
                unsigned long long a0[4], a1[4];
#pragma unroll
                for (int r = 0; r < 4; ++r) { a0[r] = 0ull; a1[r] = 0ull; }
#pragma unroll
                for (int j = 0; j < 16; ++j) {
                    ulonglong2 wv = wp[j * 64];
#pragma unroll
                    for (int r = 0; r < 4; ++r) {
                        ulonglong2 yv = yb[r * 16 + j];
                        ffma2(a0[r], yv.x, wv.x);
                        ffma2(a1[r], yv.y, wv.y);
                    }
                }
                float* rp = red0 + (t & 1) * 2048;
#pragma unroll
                for (int r = 0; r < 4; ++r) {
                    float2 f0 = *(float2*)&a0[r];
                    float2 f1 = *(float2*)&a1[r];
                    rp[r * 64] = (f0.x + f0.y) + (f1.x + f1.y);
                }
            }
            asm volatile("bar.arrive 0, %0;" :: "n"(RNT) : "memory");
        }
        // drain final in-flight phase (y_1023 into mbar[kh][1], parity 1)
        mbar_wait_parity(mbar_base + (kh * 2 + 1) * 8, 1u);
    } else {
        // =================== DYN/COMM WARPS (tid 512..767) ===================
        const int tid2 = tid - 512;             // 0..255
        const int dwarp = tid2 >> 5;            // dyn warp 0..7 (32 yn each)
        const int hl   = tid2 & 63;
        const int dh   = h0 + hl;

        const float bhh  = __ldg(&b_hh[dh]);
        const float dtal = DT_H * __ldg(&alpha[dh]);
        const float om   = __ldg(&omega[dh]);
        const float om2  = om * om;
        const float g2   = 2.f * __ldg(&gamma[dh]);
        const float vv   = __ldg(&vvec[dh]);
        const int b = bg * 4 + (tid2 >> 6);
        const float* ep = g_ext + (size_t)b * N_HID + dh;
        float*       op = out   + (size_t)b * N_HID + dh;

        float x = 0.f;
        float lin  = 0.f;                       // y + h*(-om2*x - g2*y)
        float base = GAIN_REC * bhh;            // GAIN*(bhh + vv*x)
        float ec = __ldcg((float*)ep);          // ext t
        float e1 = __ldcg((float*)(ep + YN));   // ext t+1

        for (int t = 0; t < T_STEPS; ++t) {
            asm volatile("bar.sync 0, %0;" :: "n"(RNT) : "memory");

            float acc = 0.f;
            if (t > 0) {
                const float* rp = smem + RED_F + (t & 1) * 2048 + tid2;
#pragma unroll
                for (int k = 0; k < 8; ++k)
                    acc += rp[k * 256];
            }
            float inp = ec + fmaf(GAIN_REC, acc, base);
            float th  = tanh_approx(inp);
            float yn  = fmaf(dtal, th, lin);
            float xn  = fmaf(DT_H, yn, x);
            smem[STAG_F + tid2] = yn;
            op[(size_t)t * YN] = xn;
            lin  = fmaf(DT_H, fmaf(-om2, xn, -g2 * yn), yn);
            base = GAIN_REC * fmaf(vv, xn, bhh);
            x  = xn;
            ec = e1;
            e1 = __ldcg((float*)(ep + (size_t)((t + 2) & (T_STEPS - 1)) * YN));

            // ---- eager per-warp broadcast: this warp's 32 yn = 128B ----
            __syncwarp();
            if (lane < 8) {
                asm volatile("fence.proxy.async.shared::cta;" ::: "memory");
                const uint32_t src = smem_u32
                    + (uint32_t)((STAG_F + dwarp * 32) * 4);
                const uint32_t dst = smem_u32
                    + (uint32_t)((YS_F + (t & 1) * 2048
                                  + rank * 256 + dwarp * 32) * 4);
                const uint32_t mbl = mbar_base + (rank * 2 + (t & 1)) * 8;
                bulk_s2s_128(dst, src, mbl, (uint32_t)lane);
            }
        }
    }

    asm volatile("barrier.cluster.arrive.aligned;" ::: "memory");
    asm volatile("barrier.cluster.wait.aligned;"   ::: "memory");
}

// ---------------------------------------------------------------------------
// Launch
// ---------------------------------------------------------------------------
extern "C" void kernel_launch(void* const* d_in, const int* in_sizes, int n_in,
                              void* d_out, int out_size)
{
    const float* inputs = (const float*)d_in[0];
    const float* W_ih   = (const float*)d_in[1];
    const float* b_ih   = (const float*)d_in[2];
    const float* W_hh   = (const float*)d_in[3];
    const float* b_hh   = (const float*)d_in[4];
    const float* alpha  = (const float*)d_in[5];
    const float* omega  = (const float*)d_in[6];
    const float* gamma  = (const float*)d_in[7];
    const float* v      = (const float*)d_in[8];
    float* out = (float*)d_out;

    (void)in_sizes; (void)n_in; (void)out_size;

    cudaFuncSetAttribute(horn_rec14,
                         cudaFuncAttributeMaxDynamicSharedMemorySize,
                         SMEM_R_BYTES);

    dim3 gA(N_HID / TA_N, M_TOTAL / TA_M);     // (4, 1024)
    ext_gemm_kernel<<<gA, 256>>>(inputs, W_ih, b_ih);

    horn_rec14<<<128, RNT, SMEM_R_BYTES>>>(W_hh, b_hh, alpha, omega,
                                           gamma, v, out);
}

// round 15
// speedup vs baseline: 1.0505x; 1.0505x over previous
#include <cuda_runtime.h>
#include <cuda_bf16.h>
#include <cstdint>

// ---------------------------------------------------------------------------
// Problem constants
// ---------------------------------------------------------------------------
#define T_STEPS   1024
#define BATCH     64
#define N_IN      256
#define N_HID     512
#define M_TOTAL   (T_STEPS * BATCH)       // 65536
#define YN        (BATCH * N_HID)         // 32768

#define GAIN_REC  0.04419417382415922f    // 1/sqrt(512)
#define DT_H      0.1f

__device__ float g_ext[(size_t)M_TOTAL * N_HID];   // inputs @ W_ih + b_ih

__device__ __forceinline__ void ffma2(unsigned long long& acc,
                                      unsigned long long a,
                                      unsigned long long b) {
    asm("fma.rn.f32x2 %0, %1, %2, %0;" : "+l"(acc) : "l"(a), "l"(b));
}
__device__ __forceinline__ unsigned long long pack2(float a) {
    unsigned long long r;
    asm("mov.b64 %0, {%1, %1};" : "=l"(r) : "f"(a));
    return r;
}

// ---------------------------------------------------------------------------
// Kernel A: ext = inputs @ W_ih + b_ih   (M=65536, N=512, K=256)
//   64x128 tile, 256 threads, 4x8 outputs/thread (two SPLIT 4-col groups:
//   cols [tx*4, +4) and [64+tx*4, +4) -> 16B-stride Bs loads, conflict-free).
//   f32x2 accumulation (exact fp32), register-prefetch pipeline.
// ---------------------------------------------------------------------------
#define TA_M 64
#define TA_N 128
#define TA_K 32

__global__ __launch_bounds__(256) void ext_gemm_kernel(
    const float* __restrict__ A, const float* __restrict__ W,
    const float* __restrict__ bias)
{
    __shared__ float As[TA_K][TA_M + 4];   // k-major, padded
    __shared__ float Bs[TA_K][TA_N];

    const int tid = threadIdx.x;
    const int tx  = tid & 15;              // 16 col groups
    const int ty  = tid >> 4;              // 16 row-groups of 4
    const int m0  = blockIdx.y * TA_M;
    const int n0  = blockIdx.x * TA_N;

    // per-thread load coords (2 A chunks, 4 B chunks per tile)
    int aR[2], aC[2], bR[4], bC[4];
#pragma unroll
    for (int j = 0; j < 2; ++j) {
        int f = tid + j * 256;
        aR[j] = f >> 3;  aC[j] = f & 7;
    }
#pragma unroll
    for (int j = 0; j < 4; ++j) {
        int f = tid + j * 256;
        bR[j] = f >> 5;  bC[j] = f & 31;
    }

    unsigned long long acc2[4][4];         // [row][pair]: pairs 0,1 = cols tx*4..+3
#pragma unroll                             //              pairs 2,3 = cols 64+tx*4..+3
    for (int i = 0; i < 4; ++i)
#pragma unroll
        for (int j = 0; j < 4; ++j) acc2[i][j] = 0ull;

    // prefetch tile 0 into registers
    float4 ra[2], rb[4];
#pragma unroll
    for (int j = 0; j < 2; ++j)
        ra[j] = *(const float4*)&A[(size_t)(m0 + aR[j]) * N_IN + aC[j] * 4];
#pragma unroll
    for (int j = 0; j < 4; ++j)
        rb[j] = *(const float4*)&W[(size_t)bR[j] * N_HID + n0 + bC[j] * 4];

    for (int kt = 0; kt < N_IN; kt += TA_K) {
        // commit prefetched regs to smem
#pragma unroll
        for (int j = 0; j < 2; ++j) {
            As[aC[j] * 4 + 0][aR[j]] = ra[j].x;
            As[aC[j] * 4 + 1][aR[j]] = ra[j].y;
            As[aC[j] * 4 + 2][aR[j]] = ra[j].z;
            As[aC[j] * 4 + 3][aR[j]] = ra[j].w;
        }
#pragma unroll
        for (int j = 0; j < 4; ++j)
            *(float4*)&Bs[bR[j]][bC[j] * 4] = rb[j];
        __syncthreads();

        // prefetch next tile while computing this one
        if (kt + TA_K < N_IN) {
#pragma unroll
            for (int j = 0; j < 2; ++j)
                ra[j] = *(const float4*)&A[(size_t)(m0 + aR[j]) * N_IN
                                           + kt + TA_K + aC[j] * 4];
#pragma unroll
            for (int j = 0; j < 4; ++j)
                rb[j] = *(const float4*)&W[(size_t)(kt + TA_K + bR[j]) * N_HID
                                           + n0 + bC[j] * 4];
        }

#pragma unroll
        for (int k = 0; k < TA_K; ++k) {
            float a[4];
            *(float4*)a = *(const float4*)&As[k][ty * 4];
            // two conflict-free 16B loads (16B warp stride, banks 0,4,..,60)
            ulonglong2 b0 = *(const ulonglong2*)&Bs[k][tx * 4];       // cols tx*4..+3
            ulonglong2 b1 = *(const ulonglong2*)&Bs[k][64 + tx * 4];  // cols 64+tx*4..+3
#pragma unroll
            for (int i = 0; i < 4; ++i) {
                unsigned long long pa = pack2(a[i]);
                ffma2(acc2[i][0], pa, b0.x);
                ffma2(acc2[i][1], pa, b0.y);
                ffma2(acc2[i][2], pa, b1.x);
                ffma2(acc2[i][3], pa, b1.y);
            }
        }
        __syncthreads();
    }

    // epilogue: add bias, store two float4 per row (split col groups)
    float4 bv0 = *(const float4*)&bias[n0 + tx * 4];
    float4 bv1 = *(const float4*)&bias[n0 + 64 + tx * 4];
#pragma unroll
    for (int i = 0; i < 4; ++i) {
        int m = m0 + ty * 4 + i;
        float2 p0 = *(float2*)&acc2[i][0];
        float2 p1 = *(float2*)&acc2[i][1];
        float2 p2 = *(float2*)&acc2[i][2];
        float2 p3 = *(float2*)&acc2[i][3];
        float4 o0, o1;
        o0.x = p0.x + bv0.x;  o0.y = p0.y + bv0.y;
        o0.z = p1.x + bv0.z;  o0.w = p1.y + bv0.w;
        o1.x = p2.x + bv1.x;  o1.y = p2.y + bv1.y;
        o1.z = p3.x + bv1.z;  o1.w = p3.y + bv1.w;
        *(float4*)&g_ext[(size_t)m * N_HID + n0 + tx * 4]      = o0;
        *(float4*)&g_ext[(size_t)m * N_HID + n0 + 64 + tx * 4] = o1;
    }
}

// ---------------------------------------------------------------------------
// Kernel B: persistent recurrence — BYTE-IDENTICAL to round 13 (3903us).
//   16 clusters x 8 CTAs, 768 threads; dot warps 0-15, dyn warps 16-23;
//   per-source tx-mbarriers + eager per-warp 128B bulk S2S broadcast.
// ---------------------------------------------------------------------------
#define RNT 768

#define WS_F    0                      // W slice [k4][hl] float4: 32768 floats
#define YS_F    32768                  // 2 bufs x [src(8)][row(4)][64]: 4096 f
#define RED_F   36864                  // 2 bufs x [kh(8)][row(4)][hl(64)]: 4096
#define STAG_F  40960                  // yn staging [row*64+hl]: 256 floats
#define MBAR_F  41216                  // 16 mbarriers (128 B)
#define SMEM_R_BYTES ((MBAR_F + 32) * 4)

#define TX_BYTES   1024u               // per source CTA per dest (8 x 128B)
#define CHUNK_B    128u                // per dyn-warp chunk

__device__ __forceinline__ void mbar_init(uint32_t a, uint32_t cnt) {
    asm volatile("mbarrier.init.shared.b64 [%0], %1;" :: "r"(a), "r"(cnt) : "memory");
}
__device__ __forceinline__ void mbar_expect_tx(uint32_t a, uint32_t bytes) {
    asm volatile("mbarrier.arrive.expect_tx.shared.b64 _, [%0], %1;"
                 :: "r"(a), "r"(bytes) : "memory");
}
__device__ __forceinline__ void mbar_wait_parity(uint32_t a, uint32_t par) {
    asm volatile("{\n\t.reg .pred P;\n\t"
                 "WL_%=:\n\t"
                 "mbarrier.try_wait.parity.acquire.cluster.shared::cta.b64 P, [%0], %1, 0x989680;\n\t"
                 "@P bra WD_%=;\n\t"
                 "bra WL_%=;\n\t"
                 "WD_%=:\n\t}"
                 :: "r"(a), "r"(par) : "memory");
}
__device__ __forceinline__ void bulk_s2s_128(uint32_t dstLocal, uint32_t srcLocal,
                                             uint32_t mbarLocal, uint32_t rank) {
    asm volatile("{\n\t.reg .b32 rd, rm;\n\t"
                 "mapa.shared::cluster.u32 rd, %0, %3;\n\t"
                 "mapa.shared::cluster.u32 rm, %2, %3;\n\t"
                 "cp.async.bulk.shared::cluster.shared::cta.mbarrier::complete_tx::bytes "
                 "[rd], [%1], %4, [rm];\n\t}"
                 :: "r"(dstLocal), "r"(srcLocal), "r"(mbarLocal), "r"(rank),
                    "n"(CHUNK_B)
                 : "memory");
}
__device__ __forceinline__ float tanh_approx(float x) {
    float r;
    asm("tanh.approx.f32 %0, %1;" : "=f"(r) : "f"(x));
    return r;
}

__global__ void __cluster_dims__(8, 1, 1) __launch_bounds__(RNT, 1)
horn_rec15(const float* __restrict__ W_hh,
           const float* __restrict__ b_hh,
           const float* __restrict__ alpha,
           const float* __restrict__ omega,
           const float* __restrict__ gamma,
           const float* __restrict__ vvec,
           float* __restrict__ out)
{
    extern __shared__ float smem[];

    const int tid  = threadIdx.x;
    const int bg   = blockIdx.x >> 3;           // cluster id (16)
    const int rank = blockIdx.x & 7;            // h0 = rank*64
    const int h0   = rank * 64;
    const int warp = tid >> 5;
    const int lane = tid & 31;
    const uint32_t smem_u32 = (uint32_t)__cvta_generic_to_shared(smem);
    const uint32_t mbar_base = smem_u32 + MBAR_F * 4;   // mbar[r][p] stride 8B

    // ---- fill W slice: ws[k4*256 + col*4 + (k&3)] (float4 packs a k-quad) ----
    for (int idx = tid; idx < 64 * N_HID; idx += RNT) {
        int k = idx >> 6;
        int l = idx & 63;
        smem[WS_F + (k >> 2) * 256 + l * 4 + (k & 3)] =
            W_hh[(size_t)k * N_HID + h0 + l];
    }

    if (tid < 16) mbar_init(mbar_base + tid * 8, 1);
    __syncthreads();
    if (tid < 16) mbar_expect_tx(mbar_base + tid * 8, TX_BYTES);
    __syncthreads();
    asm volatile("barrier.cluster.arrive.aligned;" ::: "memory");
    asm volatile("barrier.cluster.wait.aligned;"   ::: "memory");

    if (warp < 16) {
        // =================== DOT WARPS (tid 0..511) ===================
        const int kh = tid >> 6;                // k-slice = source rank 0..7
        const int hl = tid & 63;
        const ulonglong2* wp = ((const ulonglong2*)smem) + (kh * 16) * 64 + hl;
        float* red0 = smem + RED_F + kh * 256 + hl;

        for (int t = 0; t < T_STEPS; ++t) {
            if (t > 0) {
                const int p = (t - 1) & 1;
                const uint32_t mb = mbar_base + (kh * 2 + p) * 8;
                mbar_wait_parity(mb, (unsigned)(((t - 1) >> 1) & 1));
                if ((tid & 63) == 0) mbar_expect_tx(mb, TX_BYTES);

                // y block from source rank kh: [row(4)][64]
                const ulonglong2* yb = ((const ulonglong2*)
                    (smem + YS_F + p * 2048)) + kh * 64;
                unsigned long long a0[4], a1[4];
#pragma unroll
                for (int r = 0; r < 4; ++r) { a0[r] = 0ull; a1[r] = 0ull; }
#pragma unroll
                for (int j = 0; j < 16; ++j) {
                    ulonglong2 wv = wp[j * 64];
#pragma unroll
                    for (int r = 0; r < 4; ++r) {
                        ulonglong2 yv = yb[r * 16 + j];
                        ffma2(a0[r], yv.x, wv.x);
                        ffma2(a1[r], yv.y, wv.y);
                    }
                }
                float* rp = red0 + (t & 1) * 2048;
#pragma unroll
                for (int r = 0; r < 4; ++r) {
                    float2 f0 = *(float2*)&a0[r];
                    float2 f1 = *(float2*)&a1[r];
                    rp[r * 64] = (f0.x + f0.y) + (f1.x + f1.y);
                }
            }
            asm volatile("bar.arrive 0, %0;" :: "n"(RNT) : "memory");
        }
        // drain final in-flight phase (y_1023 into mbar[kh][1], parity 1)
        mbar_wait_parity(mbar_base + (kh * 2 + 1) * 8, 1u);
    } else {
        // =================== DYN/COMM WARPS (tid 512..767) ===================
        const int tid2 = tid - 512;             // 0..255
        const int dwarp = tid2 >> 5;            // dyn warp 0..7 (32 yn each)
        const int hl   = tid2 & 63;
        const int dh   = h0 + hl;

        const float bhh  = __ldg(&b_hh[dh]);
        const float dtal = DT_H * __ldg(&alpha[dh]);
        const float om   = __ldg(&omega[dh]);
        const float om2  = om * om;
        const float g2   = 2.f * __ldg(&gamma[dh]);
        const float vv   = __ldg(&vvec[dh]);
        const int b = bg * 4 + (tid2 >> 6);
        const float* ep = g_ext + (size_t)b * N_HID + dh;
        float*       op = out   + (size_t)b * N_HID + dh;

        float x = 0.f;
        float lin  = 0.f;                       // y + h*(-om2*x - g2*y)
        float base = GAIN_REC * bhh;            // GAIN*(bhh + vv*x)
        float ec = __ldcg((float*)ep);          // ext t
        float e1 = __ldcg((float*)(ep + YN));   // ext t+1

        for (int t = 0; t < T_STEPS; ++t) {
            asm volatile("bar.sync 0, %0;" :: "n"(RNT) : "memory");

            float acc = 0.f;
            if (t > 0) {
                const float* rp = smem + RED_F + (t & 1) * 2048 + tid2;
#pragma unroll
                for (int k = 0; k < 8; ++k)
                    acc += rp[k * 256];
            }
            float inp = ec + fmaf(GAIN_REC, acc, base);
            float th  = tanh_approx(inp);
            float yn  = fmaf(dtal, th, lin);
            float xn  = fmaf(DT_H, yn, x);
            smem[STAG_F + tid2] = yn;
            op[(size_t)t * YN] = xn;
            lin  = fmaf(DT_H, fmaf(-om2, xn, -g2 * yn), yn);
            base = GAIN_REC * fmaf(vv, xn, bhh);
            x  = xn;
            ec = e1;
            e1 = __ldcg((float*)(ep + (size_t)((t + 2) & (T_STEPS - 1)) * YN));

            // ---- eager per-warp broadcast: this warp's 32 yn = 128B ----
            __syncwarp();
            if (lane < 8) {
                asm volatile("fence.proxy.async.shared::cta;" ::: "memory");
                const uint32_t src = smem_u32
                    + (uint32_t)((STAG_F + dwarp * 32) * 4);
                const uint32_t dst = smem_u32
                    + (uint32_t)((YS_F + (t & 1) * 2048
                                  + rank * 256 + dwarp * 32) * 4);
                const uint32_t mbl = mbar_base + (rank * 2 + (t & 1)) * 8;
                bulk_s2s_128(dst, src, mbl, (uint32_t)lane);
            }
        }
    }

    asm volatile("barrier.cluster.arrive.aligned;" ::: "memory");
    asm volatile("barrier.cluster.wait.aligned;"   ::: "memory");
}

// ---------------------------------------------------------------------------
// Launch
// ---------------------------------------------------------------------------
extern "C" void kernel_launch(void* const* d_in, const int* in_sizes, int n_in,
                              void* d_out, int out_size)
{
    const float* inputs = (const float*)d_in[0];
    const float* W_ih   = (const float*)d_in[1];
    const float* b_ih   = (const float*)d_in[2];
    const float* W_hh   = (const float*)d_in[3];
    const float* b_hh   = (const float*)d_in[4];
    const float* alpha  = (const float*)d_in[5];
    const float* omega  = (const float*)d_in[6];
    const float* gamma  = (const float*)d_in[7];
    const float* v      = (const float*)d_in[8];
    float* out = (float*)d_out;

    (void)in_sizes; (void)n_in; (void)out_size;

    cudaFuncSetAttribute(horn_rec15,
                         cudaFuncAttributeMaxDynamicSharedMemorySize,
                         SMEM_R_BYTES);

    dim3 gA(N_HID / TA_N, M_TOTAL / TA_M);     // (4, 1024)
    ext_gemm_kernel<<<gA, 256>>>(inputs, W_ih, b_ih);

    horn_rec15<<<128, RNT, SMEM_R_BYTES>>>(W_hh, b_hh, alpha, omega,
                                           gamma, v, out);
}

// round 16
// speedup vs baseline: 1.2119x; 1.1536x over previous
#include <cuda_runtime.h>
#include <cuda_bf16.h>
#include <cstdint>

// ---------------------------------------------------------------------------
// Problem constants
// ---------------------------------------------------------------------------
#define T_STEPS   1024
#define BATCH     64
#define N_IN      256
#define N_HID     512
#define M_TOTAL   (T_STEPS * BATCH)       // 65536
#define YN        (BATCH * N_HID)         // 32768

#define GAIN_REC  0.04419417382415922f    // 1/sqrt(512)
#define DT_H      0.1f

__device__ float g_ext[(size_t)M_TOTAL * N_HID];   // inputs @ W_ih + b_ih

__device__ __forceinline__ void ffma2(unsigned long long& acc,
                                      unsigned long long a,
                                      unsigned long long b) {
    asm("fma.rn.f32x2 %0, %1, %2, %0;" : "+l"(acc) : "l"(a), "l"(b));
}
__device__ __forceinline__ unsigned long long pack2(float a) {
    unsigned long long r;
    asm("mov.b64 %0, {%1, %1};" : "=l"(r) : "f"(a));
    return r;
}
// bf16x2 (packed lo=k0, hi=k1) -> f32x2 ull: f32 bits = bf16 bits << 16
__device__ __forceinline__ unsigned long long bf2_to_f32x2(uint32_t u) {
    unsigned long long r;
    uint32_t lo = u << 16;
    uint32_t hi = u & 0xffff0000u;
    asm("mov.b64 %0, {%1, %2};" : "=l"(r) : "r"(lo), "r"(hi));
    return r;
}
// pack two fp32 into bf16x2 with round-to-nearest: lo=a, hi=b
__device__ __forceinline__ uint32_t f32_to_bf2(float a, float b) {
    uint32_t r;
    asm("cvt.rn.bf16x2.f32 %0, %1, %2;" : "=r"(r) : "f"(b), "f"(a));
    return r;
}

// ---------------------------------------------------------------------------
// Kernel A: ext = inputs @ W_ih + b_ih — BYTE-IDENTICAL to round 15 (361us).
//   64x128 tile, split 4-col groups (conflict-free), f32x2 accum, prefetch.
// ---------------------------------------------------------------------------
#define TA_M 64
#define TA_N 128
#define TA_K 32

__global__ __launch_bounds__(256) void ext_gemm_kernel(
    const float* __restrict__ A, const float* __restrict__ W,
    const float* __restrict__ bias)
{
    __shared__ float As[TA_K][TA_M + 4];
    __shared__ float Bs[TA_K][TA_N];

    const int tid = threadIdx.x;
    const int tx  = tid & 15;
    const int ty  = tid >> 4;
    const int m0  = blockIdx.y * TA_M;
    const int n0  = blockIdx.x * TA_N;

    int aR[2], aC[2], bR[4], bC[4];
#pragma unroll
    for (int j = 0; j < 2; ++j) {
        int f = tid + j * 256;
        aR[j] = f >> 3;  aC[j] = f & 7;
    }
#pragma unroll
    for (int j = 0; j < 4; ++j) {
        int f = tid + j * 256;
        bR[j] = f >> 5;  bC[j] = f & 31;
    }

    unsigned long long acc2[4][4];
#pragma unroll
    for (int i = 0; i < 4; ++i)
#pragma unroll
        for (int j = 0; j < 4; ++j) acc2[i][j] = 0ull;

    float4 ra[2], rb[4];
#pragma unroll
    for (int j = 0; j < 2; ++j)
        ra[j] = *(const float4*)&A[(size_t)(m0 + aR[j]) * N_IN + aC[j] * 4];
#pragma unroll
    for (int j = 0; j < 4; ++j)
        rb[j] = *(const float4*)&W[(size_t)bR[j] * N_HID + n0 + bC[j] * 4];

    for (int kt = 0; kt < N_IN; kt += TA_K) {
#pragma unroll
        for (int j = 0; j < 2; ++j) {
            As[aC[j] * 4 + 0][aR[j]] = ra[j].x;
            As[aC[j] * 4 + 1][aR[j]] = ra[j].y;
            As[aC[j] * 4 + 2][aR[j]] = ra[j].z;
            As[aC[j] * 4 + 3][aR[j]] = ra[j].w;
        }
#pragma unroll
        for (int j = 0; j < 4; ++j)
            *(float4*)&Bs[bR[j]][bC[j] * 4] = rb[j];
        __syncthreads();

        if (kt + TA_K < N_IN) {
#pragma unroll
            for (int j = 0; j < 2; ++j)
                ra[j] = *(const float4*)&A[(size_t)(m0 + aR[j]) * N_IN
                                           + kt + TA_K + aC[j] * 4];
#pragma unroll
            for (int j = 0; j < 4; ++j)
                rb[j] = *(const float4*)&W[(size_t)(kt + TA_K + bR[j]) * N_HID
                                           + n0 + bC[j] * 4];
        }

#pragma unroll
        for (int k = 0; k < TA_K; ++k) {
            float a[4];
            *(float4*)a = *(const float4*)&As[k][ty * 4];
            ulonglong2 b0 = *(const ulonglong2*)&Bs[k][tx * 4];
            ulonglong2 b1 = *(const ulonglong2*)&Bs[k][64 + tx * 4];
#pragma unroll
            for (int i = 0; i < 4; ++i) {
                unsigned long long pa = pack2(a[i]);
                ffma2(acc2[i][0], pa, b0.x);
                ffma2(acc2[i][1], pa, b0.y);
                ffma2(acc2[i][2], pa, b1.x);
                ffma2(acc2[i][3], pa, b1.y);
            }
        }
        __syncthreads();
    }

    float4 bv0 = *(const float4*)&bias[n0 + tx * 4];
    float4 bv1 = *(const float4*)&bias[n0 + 64 + tx * 4];
#pragma unroll
    for (int i = 0; i < 4; ++i) {
        int m = m0 + ty * 4 + i;
        float2 p0 = *(float2*)&acc2[i][0];
        float2 p1 = *(float2*)&acc2[i][1];
        float2 p2 = *(float2*)&acc2[i][2];
        float2 p3 = *(float2*)&acc2[i][3];
        float4 o0, o1;
        o0.x = p0.x + bv0.x;  o0.y = p0.y + bv0.y;
        o0.z = p1.x + bv0.z;  o0.w = p1.y + bv0.w;
        o1.x = p2.x + bv1.x;  o1.y = p2.y + bv1.y;
        o1.z = p3.x + bv1.z;  o1.w = p3.y + bv1.w;
        *(float4*)&g_ext[(size_t)m * N_HID + n0 + tx * 4]      = o0;
        *(float4*)&g_ext[(size_t)m * N_HID + n0 + 64 + tx * 4] = o1;
    }
}

// ---------------------------------------------------------------------------
// Kernel B: persistent recurrence — round-13/15 structure, ONE change:
//   W_hh slice stored in SMEM as packed bf16 pairs (64KB, halved crossbar).
//   y values and accumulation remain exact fp32 (FFMA2).
// ---------------------------------------------------------------------------
#define RNT 768

// SMEM layout (float-index units)
#define WS_F    0                      // W slice bf16: [k4][hl] uint2 = 16384 u32
#define YS_F    16384                  // 2 bufs x [src(8)][row(4)][64]: 4096 f
#define RED_F   20480                  // 2 bufs x [kh(8)][row(4)][hl(64)]: 4096
#define STAG_F  24576                  // yn staging [row*64+hl]: 256 floats
#define MBAR_F  24832                  // 16 mbarriers (128 B)
#define SMEM_R_BYTES ((MBAR_F + 32) * 4)

#define TX_BYTES   1024u               // per source CTA per dest (8 x 128B)
#define CHUNK_B    128u                // per dyn-warp chunk

__device__ __forceinline__ void mbar_init(uint32_t a, uint32_t cnt) {
    asm volatile("mbarrier.init.shared.b64 [%0], %1;" :: "r"(a), "r"(cnt) : "memory");
}
__device__ __forceinline__ void mbar_expect_tx(uint32_t a, uint32_t bytes) {
    asm volatile("mbarrier.arrive.expect_tx.shared.b64 _, [%0], %1;"
                 :: "r"(a), "r"(bytes) : "memory");
}
__device__ __forceinline__ void mbar_wait_parity(uint32_t a, uint32_t par) {
    asm volatile("{\n\t.reg .pred P;\n\t"
                 "WL_%=:\n\t"
                 "mbarrier.try_wait.parity.acquire.cluster.shared::cta.b64 P, [%0], %1, 0x989680;\n\t"
                 "@P bra WD_%=;\n\t"
                 "bra WL_%=;\n\t"
                 "WD_%=:\n\t}"
                 :: "r"(a), "r"(par) : "memory");
}
__device__ __forceinline__ void bulk_s2s_128(uint32_t dstLocal, uint32_t srcLocal,
                                             uint32_t mbarLocal, uint32_t rank) {
    asm volatile("{\n\t.reg .b32 rd, rm;\n\t"
                 "mapa.shared::cluster.u32 rd, %0, %3;\n\t"
                 "mapa.shared::cluster.u32 rm, %2, %3;\n\t"
                 "cp.async.bulk.shared::cluster.shared::cta.mbarrier::complete_tx::bytes "
                 "[rd], [%1], %4, [rm];\n\t}"
                 :: "r"(dstLocal), "r"(srcLocal), "r"(mbarLocal), "r"(rank),
                    "n"(CHUNK_B)
                 : "memory");
}
__device__ __forceinline__ float tanh_approx(float x) {
    float r;
    asm("tanh.approx.f32 %0, %1;" : "=f"(r) : "f"(x));
    return r;
}

__global__ void __cluster_dims__(8, 1, 1) __launch_bounds__(RNT, 1)
horn_rec16(const float* __restrict__ W_hh,
           const float* __restrict__ b_hh,
           const float* __restrict__ alpha,
           const float* __restrict__ omega,
           const float* __restrict__ gamma,
           const float* __restrict__ vvec,
           float* __restrict__ out)
{
    extern __shared__ float smem[];
    uint32_t* wsb = (uint32_t*)smem;            // bf16-pair W slice

    const int tid  = threadIdx.x;
    const int bg   = blockIdx.x >> 3;           // cluster id (16)
    const int rank = blockIdx.x & 7;            // h0 = rank*64
    const int h0   = rank * 64;
    const int warp = tid >> 5;
    const int lane = tid & 31;
    const uint32_t smem_u32 = (uint32_t)__cvta_generic_to_shared(smem);
    const uint32_t mbar_base = smem_u32 + MBAR_F * 4;   // mbar[r][p] stride 8B

    // ---- fill W slice as bf16 pairs: uint2[q*64 + l] = k-quad (4 bf16) ----
    // u32 index ((kp>>1)*64 + l)*2 + (kp&1), kp = k-pair 0..255
    for (int idx = tid; idx < 64 * (N_HID / 2); idx += RNT) {
        int kp = idx >> 6;                      // k-pair
        int l  = idx & 63;
        float f0 = W_hh[(size_t)(2 * kp)     * N_HID + h0 + l];
        float f1 = W_hh[(size_t)(2 * kp + 1) * N_HID + h0 + l];
        wsb[(((kp >> 1) * 64 + l) << 1) + (kp & 1)] = f32_to_bf2(f0, f1);
    }

    if (tid < 16) mbar_init(mbar_base + tid * 8, 1);
    __syncthreads();
    if (tid < 16) mbar_expect_tx(mbar_base + tid * 8, TX_BYTES);
    __syncthreads();
    asm volatile("barrier.cluster.arrive.aligned;" ::: "memory");
    asm volatile("barrier.cluster.wait.aligned;"   ::: "memory");

    if (warp < 16) {
        // =================== DOT WARPS (tid 0..511) ===================
        const int kh = tid >> 6;                // k-slice = source rank 0..7
        const int hl = tid & 63;
        const uint2* wp = ((const uint2*)wsb) + (kh * 16) * 64 + hl;
        float* red0 = smem + RED_F + kh * 256 + hl;

        for (int t = 0; t < T_STEPS; ++t) {
            if (t > 0) {
                const int p = (t - 1) & 1;
                const uint32_t mb = mbar_base + (kh * 2 + p) * 8;
                mbar_wait_parity(mb, (unsigned)(((t - 1) >> 1) & 1));
                if ((tid & 63) == 0) mbar_expect_tx(mb, TX_BYTES);

                // y block from source rank kh: [row(4)][64]
                const ulonglong2* yb = ((const ulonglong2*)
                    (smem + YS_F + p * 2048)) + kh * 64;
                unsigned long long a0[4], a1[4];
#pragma unroll
                for (int r = 0; r < 4; ++r) { a0[r] = 0ull; a1[r] = 0ull; }
#pragma unroll
                for (int j = 0; j < 16; ++j) {
                    uint2 wb = wp[j * 64];      // 4 bf16 k-values (LDS.64)
                    unsigned long long w01 = bf2_to_f32x2(wb.x);
                    unsigned long long w23 = bf2_to_f32x2(wb.y);
#pragma unroll
                    for (int r = 0; r < 4; ++r) {
                        ulonglong2 yv = yb[r * 16 + j];
                        ffma2(a0[r], yv.x, w01);
                        ffma2(a1[r], yv.y, w23);
                    }
                }
                float* rp = red0 + (t & 1) * 2048;
#pragma unroll
                for (int r = 0; r < 4; ++r) {
                    float2 f0 = *(float2*)&a0[r];
                    float2 f1 = *(float2*)&a1[r];
                    rp[r * 64] = (f0.x + f0.y) + (f1.x + f1.y);
                }
            }
            asm volatile("bar.arrive 0, %0;" :: "n"(RNT) : "memory");
        }
        // drain final in-flight phase (y_1023 into mbar[kh][1], parity 1)
        mbar_wait_parity(mbar_base + (kh * 2 + 1) * 8, 1u);
    } else {
        // =================== DYN/COMM WARPS (tid 512..767) ===================
        const int tid2 = tid - 512;             // 0..255
        const int dwarp = tid2 >> 5;            // dyn warp 0..7 (32 yn each)
        const int hl   = tid2 & 63;
        const int dh   = h0 + hl;

        const float bhh  = __ldg(&b_hh[dh]);
        const float dtal = DT_H * __ldg(&alpha[dh]);
        const float om   = __ldg(&omega[dh]);
        const float om2  = om * om;
        const float g2   = 2.f * __ldg(&gamma[dh]);
        const float vv   = __ldg(&vvec[dh]);
        const int b = bg * 4 + (tid2 >> 6);
        const float* ep = g_ext + (size_t)b * N_HID + dh;
        float*       op = out   + (size_t)b * N_HID + dh;

        float x = 0.f;
        float lin  = 0.f;                       // y + h*(-om2*x - g2*y)
        float base = GAIN_REC * bhh;            // GAIN*(bhh + vv*x)
        float ec = __ldcg((float*)ep);          // ext t
        float e1 = __ldcg((float*)(ep + YN));   // ext t+1

        for (int t = 0; t < T_STEPS; ++t) {
            asm volatile("bar.sync 0, %0;" :: "n"(RNT) : "memory");

            float acc = 0.f;
            if (t > 0) {
                const float* rp = smem + RED_F + (t & 1) * 2048 + tid2;
#pragma unroll
                for (int k = 0; k < 8; ++k)
                    acc += rp[k * 256];
            }
            float inp = ec + fmaf(GAIN_REC, acc, base);
            float th  = tanh_approx(inp);
            float yn  = fmaf(dtal, th, lin);
            float xn  = fmaf(DT_H, yn, x);
            smem[STAG_F + tid2] = yn;
            op[(size_t)t * YN] = xn;
            lin  = fmaf(DT_H, fmaf(-om2, xn, -g2 * yn), yn);
            base = GAIN_REC * fmaf(vv, xn, bhh);
            x  = xn;
            ec = e1;
            e1 = __ldcg((float*)(ep + (size_t)((t + 2) & (T_STEPS - 1)) * YN));

            // ---- eager per-warp broadcast: this warp's 32 yn = 128B ----
            __syncwarp();
            if (lane < 8) {
                asm volatile("fence.proxy.async.shared::cta;" ::: "memory");
                const uint32_t src = smem_u32
                    + (uint32_t)((STAG_F + dwarp * 32) * 4);
                const uint32_t dst = smem_u32
                    + (uint32_t)((YS_F + (t & 1) * 2048
                                  + rank * 256 + dwarp * 32) * 4);
                const uint32_t mbl = mbar_base + (rank * 2 + (t & 1)) * 8;
                bulk_s2s_128(dst, src, mbl, (uint32_t)lane);
            }
        }
    }

    asm volatile("barrier.cluster.arrive.aligned;" ::: "memory");
    asm volatile("barrier.cluster.wait.aligned;"   ::: "memory");
}

// ---------------------------------------------------------------------------
// Launch
// ---------------------------------------------------------------------------
extern "C" void kernel_launch(void* const* d_in, const int* in_sizes, int n_in,
                              void* d_out, int out_size)
{
    const float* inputs = (const float*)d_in[0];
    const float* W_ih   = (const float*)d_in[1];
    const float* b_ih   = (const float*)d_in[2];
    const float* W_hh   = (const float*)d_in[3];
    const float* b_hh   = (const float*)d_in[4];
    const float* alpha  = (const float*)d_in[5];
    const float* omega  = (const float*)d_in[6];
    const float* gamma  = (const float*)d_in[7];
    const float* v      = (const float*)d_in[8];
    float* out = (float*)d_out;

    (void)in_sizes; (void)n_in; (void)out_size;

    cudaFuncSetAttribute(horn_rec16,
                         cudaFuncAttributeMaxDynamicSharedMemorySize,
                         SMEM_R_BYTES);

    dim3 gA(N_HID / TA_N, M_TOTAL / TA_M);     // (4, 1024)
    ext_gemm_kernel<<<gA, 256>>>(inputs, W_ih, b_ih);

    horn_rec16<<<128, RNT, SMEM_R_BYTES>>>(W_hh, b_hh, alpha, omega,
                                           gamma, v, out);
}